// round 5
// baseline (speedup 1.0000x reference)
#include <cuda_runtime.h>
#include <math.h>

#define Bb   4
#define Tt   2048
#define Dd   1024
#define Hh   16
#define DhD  64
#define SEG  256
#define NSEG 8
#define BT   (Bb*Tt)      // 8192
#define BH   (Bb*Hh)      // 64

// ---------------- scratch (device globals; no allocations allowed) ----------
__device__ __align__(16) float g_q[BT*Dd];
__device__ __align__(16) float g_k[BT*Dd];
__device__ __align__(16) float g_v[BT*Dd];
__device__ __align__(16) float g_u[BT*Dd];
__device__ __align__(16) float g_y[BT*Dd];
__device__ __align__(16) float g_Sseg[BH*NSEG*DhD*DhD]; // per-segment sum of k(x)v
__device__ __align__(16) float g_cS  [BH*NSEG*DhD*DhD]; // prefix (cached_S[s])
__device__ __align__(16) float g_cctx[BH*NSEG*DhD];     // per-segment k sum

// ---------------- fp32 SGEMM core: C[MxN] = A[MxK] @ B[KxN], row-major ------
// BM=BN=128, BK=8, 256 threads, 8x8 per thread (split 4+4 with 64 offset).
__device__ __forceinline__ void sgemm128_body(
    const float* __restrict__ A, const float* __restrict__ Bm,
    float* __restrict__ C, int M, int N, int K,
    int brow, int bcol)
{
    __shared__ __align__(16) float As[8][128];
    __shared__ __align__(16) float Bs[8][128];

    const int tid  = threadIdx.x;

    const int a_row = tid >> 1;
    const int a_col = (tid & 1) << 2;
    const int b_row = tid >> 5;
    const int b_col = (tid & 31) << 2;

    const int trow = (tid >> 4) << 2;   // 0,4,...,60
    const int tcol = (tid & 15) << 2;   // 0,4,...,60

    float acc[8][8];
#pragma unroll
    for (int i = 0; i < 8; i++)
#pragma unroll
        for (int j = 0; j < 8; j++) acc[i][j] = 0.f;

    const float* Aptr = A + (long)(brow + a_row) * K + a_col;
    const float* Bptr = Bm + (long)b_row * N + bcol + b_col;

    for (int k0 = 0; k0 < K; k0 += 8) {
        float4 av = *(const float4*)(Aptr + k0);
        As[a_col + 0][a_row] = av.x;
        As[a_col + 1][a_row] = av.y;
        As[a_col + 2][a_row] = av.z;
        As[a_col + 3][a_row] = av.w;
        *(float4*)&Bs[b_row][b_col] = *(const float4*)(Bptr + (long)k0 * N);
        __syncthreads();
#pragma unroll
        for (int kk = 0; kk < 8; kk++) {
            float4 a0 = *(const float4*)&As[kk][trow];
            float4 a1 = *(const float4*)&As[kk][64 + trow];
            float4 b0 = *(const float4*)&Bs[kk][tcol];
            float4 b1 = *(const float4*)&Bs[kk][64 + tcol];
            float ar[8] = {a0.x,a0.y,a0.z,a0.w, a1.x,a1.y,a1.z,a1.w};
            float br[8] = {b0.x,b0.y,b0.z,b0.w, b1.x,b1.y,b1.z,b1.w};
#pragma unroll
            for (int i = 0; i < 8; i++)
#pragma unroll
                for (int j = 0; j < 8; j++) acc[i][j] += ar[i] * br[j];
        }
        __syncthreads();
    }

#pragma unroll
    for (int i = 0; i < 8; i++) {
        int r = brow + ((i < 4) ? (trow + i) : (64 + trow + i - 4));
        float4 c0 = make_float4(acc[i][0], acc[i][1], acc[i][2], acc[i][3]);
        float4 c1 = make_float4(acc[i][4], acc[i][5], acc[i][6], acc[i][7]);
        *(float4*)&C[(long)r * N + bcol + tcol]      = c0;
        *(float4*)&C[(long)r * N + bcol + 64 + tcol] = c1;
    }
}

__global__ __launch_bounds__(256) void sgemm128(
    const float* __restrict__ A, const float* __restrict__ Bm,
    float* __restrict__ C, int M, int N, int K)
{
    sgemm128_body(A, Bm, C, M, N, K, blockIdx.y * 128, blockIdx.x * 128);
}

// Fused 4-way projection GEMM: z selects which W / destination.
__global__ __launch_bounds__(256) void proj4_gemm(
    const float* __restrict__ x,
    const float* __restrict__ Wq, const float* __restrict__ Wk,
    const float* __restrict__ Wv, const float* __restrict__ Wu)
{
    const float* W;
    float* Cd;
    switch (blockIdx.z) {
        case 0: W = Wq; Cd = g_q; break;
        case 1: W = Wk; Cd = g_k; break;
        case 2: W = Wv; Cd = g_v; break;
        default: W = Wu; Cd = g_u; break;
    }
    sgemm128_body(x, W, Cd, BT, Dd, Dd, blockIdx.y * 128, blockIdx.x * 128);
}

// ---------------- per-segment sums: Sseg[b,h,s] = sum_t k (x) v; cctx = sum k
__global__ __launch_bounds__(256) void seg_sums()
{
    const int bx = blockIdx.x;        // BH*NSEG blocks
    const int s  = bx & (NSEG - 1);
    const int bh = bx >> 3;
    const int b  = bh >> 4;
    const int h  = bh & 15;
    const int tid = threadIdx.x;
    const int d  = tid >> 2;          // 0..63
    const int e0 = (tid & 3) << 4;    // 0,16,32,48

    __shared__ __align__(16) float Ks[32][64];
    __shared__ __align__(16) float Vs[32][64];

    float acc[16];
#pragma unroll
    for (int i = 0; i < 16; i++) acc[i] = 0.f;
    float ctx = 0.f;

    for (int tt = 0; tt < SEG; tt += 32) {
        __syncthreads();
        for (int i = tid; i < 512; i += 256) {           // 512 float4s per array
            int tok = i >> 4, c4 = (i & 15) << 2;
            long g = ((long)(b * Tt + s * SEG + tt + tok) * Hh + h) * DhD + c4;
            *(float4*)&Ks[tok][c4] = *(const float4*)&g_k[g];
            *(float4*)&Vs[tok][c4] = *(const float4*)&g_v[g];
        }
        __syncthreads();
#pragma unroll
        for (int j = 0; j < 32; j++) {
            float kd = Ks[j][d];
            ctx += kd;
            const float4* vr = (const float4*)&Vs[j][e0];
#pragma unroll
            for (int q4 = 0; q4 < 4; q4++) {
                float4 vv = vr[q4];
                acc[4*q4+0] += kd * vv.x;
                acc[4*q4+1] += kd * vv.y;
                acc[4*q4+2] += kd * vv.z;
                acc[4*q4+3] += kd * vv.w;
            }
        }
    }
    long base = ((long)(bh * NSEG + s) * DhD + d) * DhD + e0;
#pragma unroll
    for (int q4 = 0; q4 < 4; q4++)
        *(float4*)&g_Sseg[base + 4*q4] =
            make_float4(acc[4*q4], acc[4*q4+1], acc[4*q4+2], acc[4*q4+3]);
    if ((tid & 3) == 0) g_cctx[(bh * NSEG + s) * DhD + d] = ctx;
}

// ---------------- prefix over segments: cS[s] = sum_{s'<=s} Sseg[s'] --------
__global__ __launch_bounds__(256) void seg_prefix()
{
    const int bh = blockIdx.x;        // BH blocks
    for (int i = threadIdx.x; i < DhD * DhD; i += 256) {
        float run = 0.f;
#pragma unroll
        for (int s = 0; s < NSEG; s++) {
            long idx = ((long)(bh * NSEG + s)) * (DhD * DhD) + i;
            run += g_Sseg[idx];
            g_cS[idx] = run;
        }
    }
}

// ---------------- attention/mixing: one block per (b,h,seg), thread = token -
__global__ __launch_bounds__(256) void attn_kernel()
{
    const int bx  = blockIdx.x;       // BH*NSEG blocks
    const int seg = bx & (NSEG - 1);
    const int bh  = bx >> 3;
    const int b   = bh >> 4;
    const int h   = bh & 15;
    const int t   = threadIdx.x;      // token in segment (SEG==256==blockDim)
    const int tg  = seg * SEG + t;
    const int cur = seg;              // number of cached segments

    __shared__ __align__(16) float Ks[64][64];
    __shared__ __align__(16) float Vs[64][64];
    __shared__ __align__(16) float Cs[8][64];
    __shared__ float Wsm[8][256];     // per-token effective cached weights

    const long rowbase = ((long)(b * Tt + tg) * Hh + h) * DhD;

    // ---------- phase 1: scores ----------
    float sc[8];
    float ons = 0.f;
    {
        float ureg[64];
        const float4* up = (const float4*)&g_u[rowbase];
#pragma unroll
        for (int i = 0; i < 16; i++) {
            float4 w4 = up[i];
            ureg[4*i] = w4.x; ureg[4*i+1] = w4.y; ureg[4*i+2] = w4.z; ureg[4*i+3] = w4.w;
        }
        for (int i = t; i < cur * 64; i += 256)
            Cs[i >> 6][i & 63] = g_cctx[(bh * NSEG + (i >> 6)) * DhD + (i & 63)];
        __syncthreads();
#pragma unroll
        for (int s = 0; s < 8; s++) {
            float a = 0.f;
            if (s < cur) {
                const float4* cp = (const float4*)Cs[s];
#pragma unroll
                for (int j = 0; j < 16; j++) {
                    float4 c4 = cp[j];
                    a += ureg[4*j]*c4.x + ureg[4*j+1]*c4.y + ureg[4*j+2]*c4.z + ureg[4*j+3]*c4.w;
                }
            }
            sc[s] = a;
        }
        // on_score: causal prefix of u . k within segment (inclusive)
        for (int tile = 0; tile < 4; tile++) {
            __syncthreads();
            for (int i = t; i < 1024; i += 256) {
                int tok = i >> 4, c4 = (i & 15) << 2;
                long g = ((long)(b * Tt + seg * SEG + tile * 64 + tok) * Hh + h) * DhD + c4;
                *(float4*)&Ks[tok][c4] = *(const float4*)&g_k[g];
            }
            __syncthreads();
            int lim = t - tile * 64;
            if (lim >= 0) {
                int n = lim < 63 ? lim : 63;
                for (int tp = 0; tp <= n; tp++) {
                    const float4* kr = (const float4*)Ks[tp];
                    float a = 0.f;
#pragma unroll
                    for (int j = 0; j < 16; j++) {
                        float4 k4 = kr[j];
                        a += ureg[4*j]*k4.x + ureg[4*j+1]*k4.y + ureg[4*j+2]*k4.z + ureg[4*j+3]*k4.w;
                    }
                    ons += a;
                }
            }
        }
    }

    // ---------- softmax over [sc[0..cur-1], ons] ----------
    float wcur;
    if (cur == 0) {
        wcur = 1.f;
    } else {
        float m = ons;
#pragma unroll
        for (int s = 0; s < 8; s++) if (s < cur && sc[s] > m) m = sc[s];
        float eon = expf(ons - m);
        float denom = eon;
#pragma unroll
        for (int s = 0; s < 8; s++) {
            if (s < cur) { float e = expf(sc[s] - m); sc[s] = e; denom += e; }
        }
        float inv = 1.f / denom;
        wcur = eon * inv;
#pragma unroll
        for (int s = 0; s < 8; s++)
            if (s < cur) Wsm[s][t] = sc[s] * inv + ((s == cur - 1) ? wcur : 0.f);
    }

    // ---------- phase 2: output ----------
    float4 q4r[16];
    {
        const float4* qp = (const float4*)&g_q[rowbase];
#pragma unroll
        for (int i = 0; i < 16; i++) q4r[i] = qp[i];
    }
    float outr[64];
#pragma unroll
    for (int i = 0; i < 64; i++) outr[i] = 0.f;

    // cached-S contributions: out += wEff[s] * (q @ cS[s])
    for (int s = 0; s < cur; s++) {
        __syncthreads();
        for (int i = t; i < 1024; i += 256) {
            int dd = i >> 4, c4 = (i & 15) << 2;
            *(float4*)&Ks[dd][c4] =
                *(const float4*)&g_cS[((long)(bh * NSEG + s)) * (DhD*DhD) + dd * 64 + c4];
        }
        __syncthreads();
        float ws = Wsm[s][t];
#pragma unroll
        for (int d4 = 0; d4 < 16; d4++) {
            float4 qv = q4r[d4];
            float fq[4] = {ws*qv.x, ws*qv.y, ws*qv.z, ws*qv.w};
#pragma unroll
            for (int c = 0; c < 4; c++) {
                float f = fq[c];
                const float4* sr = (const float4*)Ks[4*d4 + c];
#pragma unroll
                for (int e = 0; e < 16; e++) {
                    float4 s4 = sr[e];
                    outr[4*e+0] += f * s4.x;
                    outr[4*e+1] += f * s4.y;
                    outr[4*e+2] += f * s4.z;
                    outr[4*e+3] += f * s4.w;
                }
            }
        }
    }

    // intra-segment causal part: out += wcur * sum_{t'<=t} (q.k_{t'}) v_{t'}
    for (int tile = 0; tile < 4; tile++) {
        __syncthreads();
        for (int i = t; i < 1024; i += 256) {
            int tok = i >> 4, c4 = (i & 15) << 2;
            long g = ((long)(b * Tt + seg * SEG + tile * 64 + tok) * Hh + h) * DhD + c4;
            *(float4*)&Ks[tok][c4] = *(const float4*)&g_k[g];
            *(float4*)&Vs[tok][c4] = *(const float4*)&g_v[g];
        }
        __syncthreads();
        int lim = t - tile * 64;
        if (lim >= 0) {
            int n = lim < 63 ? lim : 63;
            for (int tp = 0; tp <= n; tp++) {
                const float4* kr = (const float4*)Ks[tp];
                float a = 0.f;
#pragma unroll
                for (int j = 0; j < 16; j++) {
                    float4 k4 = kr[j];
                    a += q4r[j].x*k4.x + q4r[j].y*k4.y + q4r[j].z*k4.z + q4r[j].w*k4.w;
                }
                float f = wcur * a;
                const float4* vr = (const float4*)Vs[tp];
#pragma unroll
                for (int e = 0; e < 16; e++) {
                    float4 v4 = vr[e];
                    outr[4*e+0] += f * v4.x;
                    outr[4*e+1] += f * v4.y;
                    outr[4*e+2] += f * v4.z;
                    outr[4*e+3] += f * v4.w;
                }
            }
        }
    }

    float4* yp = (float4*)&g_y[rowbase];
#pragma unroll
    for (int e = 0; e < 16; e++)
        yp[e] = make_float4(outr[4*e], outr[4*e+1], outr[4*e+2], outr[4*e+3]);
}

// ---------------- launch ----------------------------------------------------
extern "C" void kernel_launch(void* const* d_in, const int* in_sizes, int n_in,
                              void* d_out, int out_size)
{
    const float* x  = (const float*)d_in[0];
    const float* Wq = (const float*)d_in[1];
    const float* Wk = (const float*)d_in[2];
    const float* Wv = (const float*)d_in[3];
    const float* Wu = (const float*)d_in[4];
    const float* Wo = (const float*)d_in[5];
    float* out = (float*)d_out;

    float* py;
    cudaGetSymbolAddress((void**)&py, g_y);

    dim3 gp(Dd / 128, BT / 128, 4);   // (8, 64, 4): fused q/k/v/u projections
    proj4_gemm<<<gp, 256>>>(x, Wq, Wk, Wv, Wu);

    seg_sums  <<<BH * NSEG, 256>>>();
    seg_prefix<<<BH,        256>>>();
    attn_kernel<<<BH * NSEG, 256>>>();

    dim3 gg(Dd / 128, BT / 128);      // (8, 64)
    sgemm128<<<gg, 256>>>(py, Wo, out, BT, Dd, Dd);
}